// round 6
// baseline (speedup 1.0000x reference)
#include <cuda_runtime.h>
#include <cstdint>

// SelfAttentionLayer fused kernel, round 4: 512 threads (16 warps) for latency hiding.
// Warp = (row-block, col-slab); weight traffic unchanged, X loads are broadcasts.
//   Q = X Wq + bq ; K = X Wk + bk ; V = X Wv + bv        (X = x[b,h] : [64,256])
//   S[w][v] = sum_c K[w][c] * Q[v][c]   (NO 1/sqrt(d) scale)
//   P = softmax over v ; O = P V ; out = O * X

#define Wn 64
#define Cn 256
#define XS 260   // padded row stride (floats); 260/4=65 odd -> conflict-free row-varying .128
#define SS 68    // padded row stride for the 64x64 score tile

#define SMEM_FLOATS (3 * Wn * XS + Wn * SS)
#define SMEM_BYTES  (SMEM_FLOATS * 4)

#define NTHREADS 512

typedef unsigned long long u64;

#define FMA2(D, A, B, C) \
    asm("fma.rn.f32x2 %0, %1, %2, %3;" : "=l"(D) : "l"(A), "l"(B), "l"(C))
#define ADD2(D, A, B) \
    asm("add.rn.f32x2 %0, %1, %2;" : "=l"(D) : "l"(A), "l"(B))

__device__ __forceinline__ u64 pk2(float lo, float hi) {
    u64 r;
    asm("mov.b64 %0, {%1, %2};" : "=l"(r) : "f"(lo), "f"(hi));
    return r;
}
__device__ __forceinline__ float2 upk2(u64 v) {
    float2 f;
    asm("mov.b64 {%0, %1}, %2;" : "=f"(f.x), "=f"(f.y) : "l"(v));
    return f;
}

// dst[64,256](+pad) = sX @ W + bias. Thread owns rows r0..r0+7, cols [c0, c0+4).
// acc[r] = 2 packed f32x2 pairs (4 channels).
__device__ __forceinline__ void proj_gemm(
    const float* __restrict__ sX, float* __restrict__ dst,
    const float* __restrict__ W, const float* __restrict__ bias,
    int r0, int c0)
{
    u64 acc[8][2];
#pragma unroll
    for (int i = 0; i < 8; i++) { acc[i][0] = 0ULL; acc[i][1] = 0ULL; }

#pragma unroll 2
    for (int k = 0; k < Cn; k += 4) {
        float4 xf[8];
#pragma unroll
        for (int r = 0; r < 8; r++)
            xf[r] = *reinterpret_cast<const float4*>(&sX[(r0 + r) * XS + k]);  // broadcast

        ulonglong2 w[4];   // 16B per lane; warp-contiguous 512B per kk
#pragma unroll
        for (int kk = 0; kk < 4; kk++)
            w[kk] = *reinterpret_cast<const ulonglong2*>(&W[(size_t)(k + kk) * Cn + c0]);

#pragma unroll
        for (int kk = 0; kk < 4; kk++) {
#pragma unroll
            for (int r = 0; r < 8; r++) {
                float xv = (kk == 0) ? xf[r].x : (kk == 1) ? xf[r].y
                         : (kk == 2) ? xf[r].z : xf[r].w;
                u64 xx = pk2(xv, xv);
                FMA2(acc[r][0], xx, w[kk].x, acc[r][0]);
                FMA2(acc[r][1], xx, w[kk].y, acc[r][1]);
            }
        }
    }

    ulonglong2 b = *reinterpret_cast<const ulonglong2*>(&bias[c0]);
#pragma unroll
    for (int r = 0; r < 8; r++) {
        ADD2(acc[r][0], acc[r][0], b.x);
        ADD2(acc[r][1], acc[r][1], b.y);
        ulonglong2 o; o.x = acc[r][0]; o.y = acc[r][1];
        *reinterpret_cast<ulonglong2*>(&dst[(r0 + r) * XS + c0]) = o;
    }
}

__global__ void __launch_bounds__(NTHREADS, 1)
attn_fused_kernel(const float* __restrict__ x,
                  const float* __restrict__ wq, const float* __restrict__ bq,
                  const float* __restrict__ wk, const float* __restrict__ bk,
                  const float* __restrict__ wv, const float* __restrict__ bv,
                  float* __restrict__ out)
{
    extern __shared__ float smem[];
    float* sX  = smem;                 // [64][260] raw input tile (kept for the gate)
    float* sQ  = sX  + Wn * XS;        // [64][260] Q
    float* sKV = sQ  + Wn * XS;        // [64][260] K, later overwritten with V
    float* sS  = sKV + Wn * XS;        // [64][68]  scores -> probabilities

    const int tid = threadIdx.x;
    const size_t bh = blockIdx.x;
    const float* xg = x   + bh * (size_t)(Wn * Cn);
    float*       og = out + bh * (size_t)(Wn * Cn);

    // ---- P0: stage X ----
    for (int i = tid; i < Wn * Cn / 4; i += NTHREADS) {
        int r = i >> 6;
        int c = (i & 63) << 2;
        float4 v = reinterpret_cast<const float4*>(xg)[i];
        *reinterpret_cast<float4*>(&sX[r * XS + c]) = v;
    }
    __syncthreads();

    const int wid  = tid >> 5;          // 0..15
    const int lane = tid & 31;
    const int r0 = (wid >> 1) << 3;     // row block: 8 rows
    const int c0 = ((wid & 1) << 7) + (lane << 2);  // col slab + lane cols

    // ---- P1: Q and K projections ----
    proj_gemm(sX, sQ,  wq, bq, r0, c0);
    proj_gemm(sX, sKV, wk, bk, r0, c0);
    __syncthreads();

    // ---- P2: S = K Q^T ; warp owns 4 q-rows, lane owns k-rows {lane, lane+32} ----
    {
        const int v0 = wid << 2;        // 4 q-rows per warp
        const int w0 = lane;
        u64 a0[4][2], a1[4][2];
#pragma unroll
        for (int j = 0; j < 4; j++) {
            a0[j][0] = a0[j][1] = 0ULL;
            a1[j][0] = a1[j][1] = 0ULL;
        }

#pragma unroll 2
        for (int c = 0; c < Cn; c += 4) {
            ulonglong2 k0 = *reinterpret_cast<const ulonglong2*>(&sKV[w0 * XS + c]);
            ulonglong2 k1 = *reinterpret_cast<const ulonglong2*>(&sKV[(w0 + 32) * XS + c]);
#pragma unroll
            for (int j = 0; j < 4; j++) {
                ulonglong2 q = *reinterpret_cast<const ulonglong2*>(&sQ[(v0 + j) * XS + c]); // broadcast
                FMA2(a0[j][0], k0.x, q.x, a0[j][0]);
                FMA2(a0[j][1], k0.y, q.y, a0[j][1]);
                FMA2(a1[j][0], k1.x, q.x, a1[j][0]);
                FMA2(a1[j][1], k1.y, q.y, a1[j][1]);
            }
        }

        float s0[4], s1[4];
#pragma unroll
        for (int j = 0; j < 4; j++) {
            float2 p00 = upk2(a0[j][0]), p01 = upk2(a0[j][1]);
            float2 p10 = upk2(a1[j][0]), p11 = upk2(a1[j][1]);
            s0[j] = (p00.x + p00.y) + (p01.x + p01.y);
            s1[j] = (p10.x + p10.y) + (p11.x + p11.y);
        }
        *reinterpret_cast<float4*>(&sS[w0 * SS + v0])        = make_float4(s0[0], s0[1], s0[2], s0[3]);
        *reinterpret_cast<float4*>(&sS[(w0 + 32) * SS + v0]) = make_float4(s1[0], s1[1], s1[2], s1[3]);
    }
    __syncthreads();

    // ---- P3: row softmax over v (warp handles rows wid*4 .. wid*4+3) ----
    {
#pragma unroll
        for (int rr = 0; rr < 4; rr++) {
            int r = (wid << 2) + rr;
            float aa = sS[r * SS + lane];
            float bb = sS[r * SS + lane + 32];
            float m = fmaxf(aa, bb);
#pragma unroll
            for (int off = 16; off > 0; off >>= 1)
                m = fmaxf(m, __shfl_xor_sync(0xffffffffu, m, off));
            float e0 = __expf(aa - m);
            float e1 = __expf(bb - m);
            float s = e0 + e1;
#pragma unroll
            for (int off = 16; off > 0; off >>= 1)
                s += __shfl_xor_sync(0xffffffffu, s, off);
            float inv = 1.0f / s;
            sS[r * SS + lane]      = e0 * inv;
            sS[r * SS + lane + 32] = e1 * inv;
        }
    }

    // ---- P4: V projection (overwrites K buffer; P2 reads done before last sync) ----
    proj_gemm(sX, sKV, wv, bv, r0, c0);
    __syncthreads();

    // ---- P5: O = P V (packed along channels), gate with X, store ----
    {
        u64 acc[8][2];
#pragma unroll
        for (int i = 0; i < 8; i++) { acc[i][0] = 0ULL; acc[i][1] = 0ULL; }

#pragma unroll 2
        for (int v = 0; v < Wn; v += 4) {
            float4 pf[8];
#pragma unroll
            for (int r = 0; r < 8; r++)
                pf[r] = *reinterpret_cast<const float4*>(&sS[(r0 + r) * SS + v]); // broadcast

            ulonglong2 va[4];
#pragma unroll
            for (int vv = 0; vv < 4; vv++)
                va[vv] = *reinterpret_cast<const ulonglong2*>(&sKV[(v + vv) * XS + c0]);

#pragma unroll
            for (int vv = 0; vv < 4; vv++) {
#pragma unroll
                for (int r = 0; r < 8; r++) {
                    float p = (vv == 0) ? pf[r].x : (vv == 1) ? pf[r].y
                            : (vv == 2) ? pf[r].z : pf[r].w;
                    u64 pp = pk2(p, p);
                    FMA2(acc[r][0], pp, va[vv].x, acc[r][0]);
                    FMA2(acc[r][1], pp, va[vv].y, acc[r][1]);
                }
            }
        }

#pragma unroll
        for (int r = 0; r < 8; r++) {
            float4 xr = *reinterpret_cast<const float4*>(&sX[(r0 + r) * XS + c0]);
            float2 a0 = upk2(acc[r][0]), a1 = upk2(acc[r][1]);
            float4 o = make_float4(a0.x * xr.x, a0.y * xr.y, a1.x * xr.z, a1.y * xr.w);
            *reinterpret_cast<float4*>(&og[(r0 + r) * Cn + c0]) = o;
        }
    }
}

extern "C" void kernel_launch(void* const* d_in, const int* in_sizes, int n_in,
                              void* d_out, int out_size)
{
    const float* x  = (const float*)d_in[0];
    const float* wq = (const float*)d_in[1];
    const float* bq = (const float*)d_in[2];
    const float* wk = (const float*)d_in[3];
    const float* bk = (const float*)d_in[4];
    const float* wv = (const float*)d_in[5];
    const float* bv = (const float*)d_in[6];
    float* out = (float*)d_out;

    int n_bh = in_sizes[0] / (Wn * Cn);   // B*H = 2048

    cudaFuncSetAttribute(attn_fused_kernel,
                         cudaFuncAttributeMaxDynamicSharedMemorySize, SMEM_BYTES);
    attn_fused_kernel<<<n_bh, NTHREADS, SMEM_BYTES>>>(x, wq, bq, wk, bk, wv, bv, out);
}